// round 15
// baseline (speedup 1.0000x reference)
#include <cuda_runtime.h>
#include <cuda_fp16.h>
#include <math.h>

// Problem constants (fixed shapes for GAT_76184129896720)
#define NN 30000
#define NPAD 30080           // 235 * 128
#define EE 480000
#define EMB 256
#define GG 512
#define NEG_SLOPE 0.2f
#define SCB 30
#define EBLOCKS 1875         // (EE+255)/256
#define NWB 3750             // NN/8 warp-per-node blocks

// node split for layer-boundary pipelining (multiple of 128)
#define NSPLIT 15104         // A: rows [0,15104) = 118 tiles; B: [15104,NPAD) = 117
#define NWB_A 1888           // 15104/8
#define NWB_B 1862           // ceil((30000-15104)/8)

// ---------------- device scratch (static; no allocations allowed) ----------
__device__ __half  g_h16[NPAD * EMB];  // node features (fp16 residual stream)
__device__ __half  g_w16[3 * EMB * EMB]; // per-layer W, fp16, transposed [n][k]
__device__ __half  g_emb16[9 * 128 * EMB]; // fp16 atom embedding tables
__device__ __half2 g_xlh0[NPAD * 128]; // xl buffers, double-buffered by layer parity
__device__ __half2 g_xlh1[NPAD * 128];
__device__ float   g_asL[3 * NN];      // per-layer xl.att_src (epilogue-fused)
__device__ float   g_adL[3 * NN];      // per-layer xl.att_dst
__device__ int     g_deg[NN];
__device__ int     g_rowptr[NN + 1];
__device__ int     g_cursor[NN];
__device__ uint2   g_csr[EE];          // packed {src, bond attrs} per CSR slot
__device__ int     g_bsum[SCB];
__device__ int     g_boff[SCB];
__device__ float   g_dtable[3 * 48];
__device__ float   g_wv[EMB];
__device__ float   g_bconst;
__device__ float   g_gsum[GG];
__device__ float   g_gcnt[GG];

// ---------------- helpers ---------------------------------------------------
__device__ __forceinline__ float warp_sum(float v) {
#pragma unroll
    for (int o = 16; o > 0; o >>= 1) v += __shfl_xor_sync(0xffffffffu, v, o);
    return v;
}
__device__ __forceinline__ int warp_sum_i(int v) {
#pragma unroll
    for (int o = 16; o > 0; o >>= 1) v += __shfl_xor_sync(0xffffffffu, v, o);
    return v;
}
__device__ __forceinline__ void cp16(unsigned dst, const void* src) {
    asm volatile("cp.async.cg.shared.global [%0], [%1], 16;" :: "r"(dst), "l"(src));
}
__device__ __forceinline__ void ldsm4(unsigned addr, unsigned& r0, unsigned& r1,
                                      unsigned& r2, unsigned& r3) {
    asm volatile("ldmatrix.sync.aligned.m8n8.x4.shared.b16 {%0,%1,%2,%3}, [%4];"
                 : "=r"(r0), "=r"(r1), "=r"(r2), "=r"(r3) : "r"(addr));
}
__device__ __forceinline__ int swoff(int m, int kc) {
    int p = m >> 1;
    int c = ((m & 1) << 2) | (kc ^ (p & 3));
    return p * 128 + c * 16;
}
__device__ __forceinline__ void fma8(float* acc, float wv, const uint4& v) {
    const __half2* h2 = (const __half2*)&v;
    float2 f0 = __half22float2(h2[0]), f1 = __half22float2(h2[1]);
    float2 f2 = __half22float2(h2[2]), f3 = __half22float2(h2[3]);
    acc[0] += wv * f0.x; acc[1] += wv * f0.y;
    acc[2] += wv * f1.x; acc[3] += wv * f1.y;
    acc[4] += wv * f2.x; acc[5] += wv * f2.y;
    acc[6] += wv * f3.x; acc[7] += wv * f3.y;
}
__device__ __forceinline__ __half2* xlbuf(int l) {
    return (l & 1) ? g_xlh1 : g_xlh0;
}

// ---------------- setup, split for stream overlap ----------------------------
__global__ void k_setup_emb(const float* __restrict__ emb) {
    int idx = blockIdx.x * 1536 + threadIdx.x;  // 192 blocks
#pragma unroll
    for (int j = 0; j < 6; j++) {
        g_emb16[idx] = __float2half(emb[idx]);
        idx += 256;
    }
}

#define INIT_BLKS 352
#define WCONV_BLKS 192
__global__ void k_setup_rest(const float* __restrict__ W,
                             const float* __restrict__ W1, const float* __restrict__ b1,
                             const float* __restrict__ W2, const float* __restrict__ b2,
                             const float* __restrict__ We, const float* __restrict__ att_edge,
                             const float* __restrict__ bond_emb) {
    int t = threadIdx.x;  // 256
    int bid = blockIdx.x;
    if (bid < INIT_BLKS) {
        int i = bid * 256 + t;
        if (i < NN) { g_deg[i] = 0; g_cursor[i] = 0; }
        if (i < GG) { g_gsum[i] = 0.f; g_gcnt[i] = 0.f; }
        if (i < (NPAD - NN) * EMB) g_h16[NN * EMB + i] = __float2half(0.f);
        if (i < 3 * NN) { g_asL[i] = 0.f; g_adL[i] = 0.f; }
    } else if (bid < INIT_BLKS + WCONV_BLKS) {
        int wb = bid - INIT_BLKS;       // 0..191
        int l = wb >> 6;
        int rem = wb & 63;
        int kb = (rem & 7) * 32, nb = (rem >> 3) * 32;
        int tx = t & 31, ty = t >> 5;
        __shared__ float tile[32][33];
        for (int i = ty; i < 32; i += 8)
            tile[i][tx] = W[(size_t)l * EMB * EMB + (kb + i) * EMB + nb + tx];
        __syncthreads();
        for (int i = ty; i < 32; i += 8)
            g_w16[(size_t)l * EMB * EMB + (nb + i) * EMB + kb + tx] =
                __float2half(tile[tx][i]);
    } else if (bid == INIT_BLKS + WCONV_BLKS) {
        int c = t;
        float acc = 0.f;
#pragma unroll 8
        for (int j = 0; j < EMB; j++) acc += W1[c * EMB + j] * W2[j];
        g_wv[c] = acc;
        __shared__ float sh[EMB];
        sh[c] = b1[c] * W2[c];
        __syncthreads();
        for (int s = 128; s > 0; s >>= 1) {
            if (c < s) sh[c] += sh[c + s];
            __syncthreads();
        }
        if (c == 0) g_bconst = sh[0] + b2[0];
    } else {
        int l = bid - (INIT_BLKS + WCONV_BLKS + 1);
        __shared__ float wa[3];
        int w = t >> 5, lane = t & 31;
        if (w < 3) {
            float p = 0.f;
            for (int k = lane; k < EMB; k += 32)
                p += We[(l * 3 + w) * EMB + k] * att_edge[l * EMB + k];
            p = warp_sum(p);
            if (lane == 0) wa[w] = p;
        }
        __syncthreads();
        if (t < 48) {
            int j = t >> 4, v = t & 15;
            const float* be = bond_emb + ((size_t)(l * 3 + j) * 16 + v) * 3;
            g_dtable[l * 48 + t] = be[0] * wa[0] + be[1] * wa[1] + be[2] * wa[2];
        }
    }
}

// AtomEncoder, warp-per-node
__global__ void k_atom(const int* __restrict__ x) {
    int t = threadIdx.x;  // 256
    int lane = t & 31;
    int gw = blockIdx.x * 8 + (t >> 5);
    int xv = (lane < 9) ? x[gw * 9 + lane] : 0;
    float acc[8] = {0, 0, 0, 0, 0, 0, 0, 0};
#pragma unroll
    for (int i = 0; i < 9; i++) {
        int xi = __shfl_sync(0xffffffffu, xv, i);
        uint4 v = *(const uint4*)(g_emb16 + ((size_t)(i * 128 + xi)) * EMB + lane * 8);
        fma8(acc, 1.0f, v);
    }
    __half2 o[4];
    o[0] = __floats2half2_rn(acc[0], acc[1]);
    o[1] = __floats2half2_rn(acc[2], acc[3]);
    o[2] = __floats2half2_rn(acc[4], acc[5]);
    o[3] = __floats2half2_rn(acc[6], acc[7]);
    *(uint4*)(g_h16 + (size_t)gw * EMB + lane * 8) = *(uint4*)o;
}

__global__ void k_hist(const int* __restrict__ dst) {
    int e = blockIdx.x * blockDim.x + threadIdx.x;
    if (e < EE) atomicAdd(&g_deg[dst[e]], 1);
}

// --------- 3-phase multi-block exclusive scan of g_deg -> g_rowptr ----------
__global__ void k_scan_red() {
    __shared__ int ws[32];
    int t = threadIdx.x, lane = t & 31, wid = t >> 5;
    int idx = blockIdx.x * 1024 + t;
    int v = (idx < NN) ? g_deg[idx] : 0;
    v = warp_sum_i(v);
    if (lane == 0) ws[wid] = v;
    __syncthreads();
    if (wid == 0) {
        int s = ws[lane];
        s = warp_sum_i(s);
        if (lane == 0) g_bsum[blockIdx.x] = s;
    }
}
__global__ void k_scan_top() {
    int lane = threadIdx.x;
    int v = (lane < SCB) ? g_bsum[lane] : 0;
    int x = v;
#pragma unroll
    for (int o = 1; o < 32; o <<= 1) {
        int y = __shfl_up_sync(0xffffffffu, x, o);
        if (lane >= o) x += y;
    }
    if (lane < SCB) g_boff[lane] = x - v;
}
__global__ void k_scan_low() {
    __shared__ int ws[32];
    int t = threadIdx.x, lane = t & 31, wid = t >> 5;
    int idx = blockIdx.x * 1024 + t;
    int v = (idx < NN) ? g_deg[idx] : 0;
    int x = v;
#pragma unroll
    for (int o = 1; o < 32; o <<= 1) {
        int y = __shfl_up_sync(0xffffffffu, x, o);
        if (lane >= o) x += y;
    }
    if (lane == 31) ws[wid] = x;
    __syncthreads();
    if (wid == 0) {
        int w = ws[lane];
#pragma unroll
        for (int o = 1; o < 32; o <<= 1) {
            int y = __shfl_up_sync(0xffffffffu, w, o);
            if (lane >= o) w += y;
        }
        ws[lane] = w;
    }
    __syncthreads();
    int incl = x + ((wid > 0) ? ws[wid - 1] : 0) + g_boff[blockIdx.x];
    if (idx < NN) g_rowptr[idx + 1] = incl;
    if (idx == 0) g_rowptr[0] = 0;
}

__global__ void k_scatter(const int* __restrict__ src, const int* __restrict__ dst,
                          const int* __restrict__ ea) {
    int e = blockIdx.x * blockDim.x + threadIdx.x;
    if (e >= EE) return;
    int d = dst[e];
    int pos = g_rowptr[d] + atomicAdd(&g_cursor[d], 1);
    unsigned packed = (unsigned)ea[e * 3 + 0] | ((unsigned)ea[e * 3 + 1] << 8) |
                      ((unsigned)ea[e * 3 + 2] << 16);
    g_csr[pos] = make_uint2((unsigned)src[e], packed);
}

// ------- fp16 GEMM + fused as/ad epilogue (row-range via rbase) --------------
__global__ __launch_bounds__(256, 2) void k_mma(int l, int rbase,
                                                const float* __restrict__ att_s,
                                                const float* __restrict__ att_d) {
    __shared__ __align__(16) char sm[49152];
    const unsigned smb = (unsigned)__cvta_generic_to_shared(sm);
    const int tid = threadIdx.x;
    const int lane = tid & 31;
    const int w = tid >> 5;
    const int tig = lane & 3, gid = lane >> 2;
    const int warp_m = w >> 2, warp_n = w & 3;
    const int r0 = rbase + blockIdx.x * 128, c0 = blockIdx.y * 128;
    __half2* xl = xlbuf(l);

    const int lm = tid & 127;
    const int lkc = (tid >> 7) * 2;
    const __half* Ag = g_h16 + (size_t)(r0 + lm) * EMB + lkc * 8;
    const __half* Bg = g_w16 + (size_t)l * EMB * EMB + (size_t)(c0 + lm) * EMB + lkc * 8;
    const int sA0 = swoff(lm, lkc), sA1 = swoff(lm, lkc + 1);

    float acc[16][4];
#pragma unroll
    for (int i = 0; i < 16; i++)
#pragma unroll
        for (int j = 0; j < 4; j++) acc[i][j] = 0.f;

#define ISSUE(s)                                                          \
    {                                                                     \
        unsigned st = smb + ((s) % 3) * 16384;                            \
        cp16(st + sA0, Ag + (s) * 32);                                    \
        cp16(st + sA1, Ag + (s) * 32 + 8);                                \
        cp16(st + 8192 + sA0, Bg + (s) * 32);                             \
        cp16(st + 8192 + sA1, Bg + (s) * 32 + 8);                         \
        asm volatile("cp.async.commit_group;");                           \
    }

    ISSUE(0);
    ISSUE(1);

#pragma unroll
    for (int s = 0; s < 8; s++) {
        if (s < 7) asm volatile("cp.async.wait_group 1;");
        else       asm volatile("cp.async.wait_group 0;");
        __syncthreads();
        if (s + 2 < 8) ISSUE(s + 2);
        unsigned Ab = smb + (s % 3) * 16384;
        unsigned Bb = Ab + 8192;
#pragma unroll
        for (int kk = 0; kk < 32; kk += 16) {
            unsigned af[4][4], bf[4][2];
#pragma unroll
            for (int mt = 0; mt < 4; mt++) {
                int r = warp_m * 64 + mt * 16 + (lane & 15);
                int kc = (kk >> 3) + (lane >> 4);
                ldsm4(Ab + swoff(r, kc), af[mt][0], af[mt][1], af[mt][2], af[mt][3]);
            }
#pragma unroll
            for (int pr = 0; pr < 2; pr++) {
                int n = warp_n * 32 + pr * 16 + ((lane >> 4) & 1) * 8 + (lane & 7);
                int kc = (kk >> 3) + ((lane >> 3) & 1);
                ldsm4(Bb + swoff(n, kc), bf[2 * pr][0], bf[2 * pr][1],
                      bf[2 * pr + 1][0], bf[2 * pr + 1][1]);
            }
#pragma unroll
            for (int mt = 0; mt < 4; mt++)
#pragma unroll
                for (int nt = 0; nt < 4; nt++) {
                    float* c = acc[mt * 4 + nt];
                    asm volatile(
                        "mma.sync.aligned.m16n8k16.row.col.f32.f16.f16.f32 "
                        "{%0,%1,%2,%3}, {%4,%5,%6,%7}, {%8,%9}, {%0,%1,%2,%3};"
                        : "+f"(c[0]), "+f"(c[1]), "+f"(c[2]), "+f"(c[3])
                        : "r"(af[mt][0]), "r"(af[mt][1]), "r"(af[mt][2]), "r"(af[mt][3]),
                          "r"(bf[nt][0]), "r"(bf[nt][1]));
                }
        }
    }
#undef ISSUE
    float* asbuf = g_asL + l * NN;
    float* adbuf = g_adL + l * NN;
#pragma unroll
    for (int mt = 0; mt < 4; mt++) {
        int r = r0 + warp_m * 64 + mt * 16 + gid;
        float ps = 0.f, pd = 0.f, qs = 0.f, qd = 0.f;
#pragma unroll
        for (int nt = 0; nt < 4; nt++) {
            int c = c0 + warp_n * 32 + nt * 8 + 2 * tig;
            int ch = c >> 1;
            const float* a = acc[mt * 4 + nt];
            xl[(size_t)r * 128 + ch] = __floats2half2_rn(a[0], a[1]);
            xl[(size_t)(r + 8) * 128 + ch] = __floats2half2_rn(a[2], a[3]);
            float s0 = att_s[c], s1 = att_s[c + 1];
            float d0 = att_d[c], d1 = att_d[c + 1];
            ps += a[0] * s0 + a[1] * s1;
            pd += a[0] * d0 + a[1] * d1;
            qs += a[2] * s0 + a[3] * s1;
            qd += a[2] * d0 + a[3] * d1;
        }
#pragma unroll
        for (int o = 1; o <= 2; o <<= 1) {
            ps += __shfl_xor_sync(0xffffffffu, ps, o);
            pd += __shfl_xor_sync(0xffffffffu, pd, o);
            qs += __shfl_xor_sync(0xffffffffu, qs, o);
            qd += __shfl_xor_sync(0xffffffffu, qd, o);
        }
        if (tig == 0) {
            if (r < NN) { atomicAdd(asbuf + r, ps); atomicAdd(adbuf + r, pd); }
            if (r + 8 < NN) { atomicAdd(asbuf + r + 8, qs); atomicAdd(adbuf + r + 8, qd); }
        }
    }
}

// fused attention over node range [nbase, nend), BATCH-8 gather
__global__ void k_att(const float* __restrict__ bias, int do_relu, int l,
                      const int* __restrict__ batch, int do_pool,
                      int nbase, int nend) {
    __shared__ float sdt[48];
    int t = threadIdx.x;
    if (t < 48) sdt[t] = g_dtable[l * 48 + t];
    __syncthreads();
    int gw = nbase + ((blockIdx.x * blockDim.x + t) >> 5);
    int lane = t & 31;
    if (gw >= nend) return;
    const __half2* xl = xlbuf(l);
    const float* asv = g_asL + l * NN;
    const float* adv = g_adL + l * NN;
    int start = g_rowptr[gw], end = g_rowptr[gw + 1];
    float adn = adv[gw];
    uint4 hv = *(const uint4*)(g_h16 + (size_t)gw * EMB + lane * 8);

    float acc[8] = {0, 0, 0, 0, 0, 0, 0, 0};
    float denom = 0.f, esum = 0.f;
    for (int cb = start; cb < end; cb += 32) {
        int pos = cb + lane;
        float p = 0.f;
        int s = 0;
        if (pos < end) {
            uint2 se = g_csr[pos];
            s = (int)se.x;
            unsigned ea = se.y;
            float ed = sdt[ea & 15] + sdt[16 + ((ea >> 8) & 15)] +
                       sdt[32 + ((ea >> 16) & 15)];
            float a = asv[s] + adn + ed;
            a = (a >= 0.f) ? a : NEG_SLOPE * a;
            p = __expf(a);
            esum += ed;
        }
        denom += p;
        int cnt = min(32, end - cb);
        for (int i = 0; i < cnt; i += 8) {
            float w0 = __shfl_sync(0xffffffffu, p, i);
            int   s0 = __shfl_sync(0xffffffffu, s, i);
#define BCAST(j) \
            float w##j = (i + j < 32) ? __shfl_sync(0xffffffffu, p, i + j) : 0.f; \
            int   s##j = (i + j < 32) ? __shfl_sync(0xffffffffu, s, i + j) : 0;
            BCAST(1) BCAST(2) BCAST(3) BCAST(4) BCAST(5) BCAST(6) BCAST(7)
#undef BCAST
            uint4 v0 = make_uint4(0, 0, 0, 0), v1 = v0, v2 = v0, v3 = v0;
            uint4 v4 = v0, v5 = v0, v6 = v0, v7 = v0;
            if (w0 > 0.f) v0 = *(const uint4*)(xl + (size_t)s0 * 128 + lane * 4);
            if (w1 > 0.f) v1 = *(const uint4*)(xl + (size_t)s1 * 128 + lane * 4);
            if (w2 > 0.f) v2 = *(const uint4*)(xl + (size_t)s2 * 128 + lane * 4);
            if (w3 > 0.f) v3 = *(const uint4*)(xl + (size_t)s3 * 128 + lane * 4);
            if (w4 > 0.f) v4 = *(const uint4*)(xl + (size_t)s4 * 128 + lane * 4);
            if (w5 > 0.f) v5 = *(const uint4*)(xl + (size_t)s5 * 128 + lane * 4);
            if (w6 > 0.f) v6 = *(const uint4*)(xl + (size_t)s6 * 128 + lane * 4);
            if (w7 > 0.f) v7 = *(const uint4*)(xl + (size_t)s7 * 128 + lane * 4);
            fma8(acc, w0, v0);
            fma8(acc, w1, v1);
            fma8(acc, w2, v2);
            fma8(acc, w3, v3);
            fma8(acc, w4, v4);
            fma8(acc, w5, v5);
            fma8(acc, w6, v6);
            fma8(acc, w7, v7);
        }
    }
    // self loop
    {
        esum = warp_sum(esum);
        int deg = end - start;
        float selfa = asv[gw] + adn + esum / fmaxf((float)deg, 1.0f);
        selfa = (selfa >= 0.f) ? selfa : NEG_SLOPE * selfa;
        float wv = __expf(selfa);
        denom = warp_sum(denom) + wv;
        uint4 v = *(const uint4*)(xl + (size_t)gw * 128 + lane * 4);
        fma8(acc, wv, v);
    }
    float inv = 1.0f / denom;
    const __half2* hh = (const __half2*)&hv;
    float2 hf0 = __half22float2(hh[0]), hf1 = __half22float2(hh[1]);
    float2 hf2 = __half22float2(hh[2]), hf3 = __half22float2(hh[3]);
    const float4* b4 = (const float4*)(bias + lane * 8);
    float4 b0 = b4[0], b1 = b4[1];
    float r[8];
    r[0] = acc[0] * inv + b0.x; r[1] = acc[1] * inv + b0.y;
    r[2] = acc[2] * inv + b0.z; r[3] = acc[3] * inv + b0.w;
    r[4] = acc[4] * inv + b1.x; r[5] = acc[5] * inv + b1.y;
    r[6] = acc[6] * inv + b1.z; r[7] = acc[7] * inv + b1.w;
    if (do_relu) {
#pragma unroll
        for (int j = 0; j < 8; j++) r[j] = fmaxf(r[j], 0.f);
    }
    r[0] += hf0.x; r[1] += hf0.y; r[2] += hf1.x; r[3] += hf1.y;
    r[4] += hf2.x; r[5] += hf2.y; r[6] += hf3.x; r[7] += hf3.y;
    if (do_pool) {
        const float4* w4 = (const float4*)(g_wv + lane * 8);
        float4 w0 = w4[0], w1 = w4[1];
        float sdot = r[0] * w0.x + r[1] * w0.y + r[2] * w0.z + r[3] * w0.w +
                     r[4] * w1.x + r[5] * w1.y + r[6] * w1.z + r[7] * w1.w;
        sdot = warp_sum(sdot);
        if (lane == 0) {
            int g = batch[gw];
            atomicAdd(&g_gsum[g], sdot);
            atomicAdd(&g_gcnt[g], 1.0f);
        }
    } else {
        __half2 o[4];
        o[0] = __floats2half2_rn(r[0], r[1]);
        o[1] = __floats2half2_rn(r[2], r[3]);
        o[2] = __floats2half2_rn(r[4], r[5]);
        o[3] = __floats2half2_rn(r[6], r[7]);
        *(uint4*)(g_h16 + (size_t)gw * EMB + lane * 8) = *(uint4*)o;
    }
}

__global__ void k_final(float* __restrict__ out) {
    int g = blockIdx.x * blockDim.x + threadIdx.x;
    if (g < GG) out[g] = g_gsum[g] / fmaxf(g_gcnt[g], 1.0f) + g_bconst;
}

// ---------------- launch -----------------------------------------------------
extern "C" void kernel_launch(void* const* d_in, const int* in_sizes, int n_in,
                              void* d_out, int out_size) {
    const int* x = (const int*)d_in[0];
    const int* edge_index = (const int*)d_in[1];
    const int* edge_attr = (const int*)d_in[2];
    const int* batch = (const int*)d_in[3];
    const float* atom_emb = (const float*)d_in[4];
    const float* bond_emb = (const float*)d_in[5];
    const float* W = (const float*)d_in[6];
    const float* att_src = (const float*)d_in[7];
    const float* att_dst = (const float*)d_in[8];
    const float* We = (const float*)d_in[9];
    const float* att_edge = (const float*)d_in[10];
    const float* bias = (const float*)d_in[11];
    const float* W1 = (const float*)d_in[12];
    const float* b1 = (const float*)d_in[13];
    const float* W2 = (const float*)d_in[14];
    const float* b2 = (const float*)d_in[15];
    float* out = (float*)d_out;

    const int* src = edge_index;
    const int* dst = edge_index + EE;

    // Side stream + events (host handles only; created fresh per call,
    // intentionally not destroyed while possibly participating in capture).
    cudaStream_t s2;
    cudaStreamCreateWithFlags(&s2, cudaStreamNonBlocking);
    cudaEvent_t efork, ew16, ejoin, eA[2], eM[2];
    cudaEventCreateWithFlags(&efork, cudaEventDisableTiming);
    cudaEventCreateWithFlags(&ew16, cudaEventDisableTiming);
    cudaEventCreateWithFlags(&ejoin, cudaEventDisableTiming);
    for (int i = 0; i < 2; i++) {
        cudaEventCreateWithFlags(&eA[i], cudaEventDisableTiming);
        cudaEventCreateWithFlags(&eM[i], cudaEventDisableTiming);
    }

    cudaEventRecord(efork, 0);
    cudaStreamWaitEvent(s2, efork, 0);

    // prologue: main = emb->atom->mma0 ; side = rest->hist->scan->scatter
    k_setup_emb<<<192, 256>>>(atom_emb);
    k_setup_rest<<<INIT_BLKS + WCONV_BLKS + 4, 256, 0, s2>>>(W, W1, b1, W2, b2,
                                                             We, att_edge, bond_emb);
    cudaEventRecord(ew16, s2);
    k_atom<<<NWB, 256>>>(x);
    k_hist<<<EBLOCKS, 256, 0, s2>>>(dst);
    cudaStreamWaitEvent(0, ew16, 0);
    k_mma<<<dim3(235, 2), 256>>>(0, 0, att_src, att_dst);
    k_scan_red<<<SCB, 1024, 0, s2>>>();
    k_scan_top<<<1, 32, 0, s2>>>();
    k_scan_low<<<SCB, 1024, 0, s2>>>();
    k_scatter<<<EBLOCKS, 256, 0, s2>>>(src, dst, edge_attr);
    cudaEventRecord(ejoin, s2);
    cudaStreamWaitEvent(0, ejoin, 0);

    // layer loop with boundary pipelining:
    // att_A(l) -> [side: mma_A(l+1)] || att_B(l) -> mma_B(l+1) -> join
    for (int l = 0; l < 3; l++) {
        int relu = (l < 2) ? 1 : 0, pool = (l == 2) ? 1 : 0;
        k_att<<<NWB_A, 256>>>(bias + l * EMB, relu, l, batch, pool, 0, NSPLIT);
        if (l < 2) {
            cudaEventRecord(eA[l], 0);
            cudaStreamWaitEvent(s2, eA[l], 0);
            k_mma<<<dim3(118, 2), 256, 0, s2>>>(l + 1, 0, att_src + (l + 1) * EMB,
                                                att_dst + (l + 1) * EMB);
            cudaEventRecord(eM[l], s2);
        }
        k_att<<<NWB_B, 256>>>(bias + l * EMB, relu, l, batch, pool, NSPLIT, NN);
        if (l < 2) {
            k_mma<<<dim3(117, 2), 256>>>(l + 1, NSPLIT, att_src + (l + 1) * EMB,
                                         att_dst + (l + 1) * EMB);
            cudaStreamWaitEvent(0, eM[l], 0);
        }
    }

    k_final<<<2, 256>>>(out);
}

// round 16
// speedup vs baseline: 1.0432x; 1.0432x over previous
#include <cuda_runtime.h>
#include <cuda_fp16.h>
#include <math.h>

// Problem constants (fixed shapes for GAT_76184129896720)
#define NN 30000
#define NPAD 30080           // 235 * 128
#define EE 480000
#define EMB 256
#define GG 512
#define NEG_SLOPE 0.2f
#define SCB 30
#define EBLOCKS 1875         // (EE+255)/256
#define NWB 3750             // NN/8 warp-per-node blocks

// ---------------- device scratch (static; no allocations allowed) ----------
__device__ __half  g_h16[NPAD * EMB];  // node features (fp16 residual stream)
__device__ __half  g_w16[3 * EMB * EMB]; // per-layer W, fp16, transposed [n][k]
__device__ __half  g_emb16[9 * 128 * EMB]; // fp16 atom embedding tables
__device__ __half2 g_xlh[NPAD * 128];  // h @ W[l] in fp16 (256 halves per row)
__device__ float   g_asL[3 * NN];      // per-layer xl.att_src (epilogue-fused)
__device__ float   g_adL[3 * NN];      // per-layer xl.att_dst
__device__ int     g_deg[NN];
__device__ int     g_rowptr[NN + 1];
__device__ int     g_cursor[NN];
__device__ uint2   g_csr[EE];          // packed {src, bond attrs} per CSR slot
__device__ int     g_bsum[SCB];
__device__ int     g_boff[SCB];
__device__ float   g_dtable[3 * 48];
__device__ float   g_wv[EMB];
__device__ float   g_bconst;
__device__ float   g_gsum[GG];
__device__ float   g_gcnt[GG];

// ---------------- helpers ---------------------------------------------------
__device__ __forceinline__ float warp_sum(float v) {
#pragma unroll
    for (int o = 16; o > 0; o >>= 1) v += __shfl_xor_sync(0xffffffffu, v, o);
    return v;
}
__device__ __forceinline__ int warp_sum_i(int v) {
#pragma unroll
    for (int o = 16; o > 0; o >>= 1) v += __shfl_xor_sync(0xffffffffu, v, o);
    return v;
}
__device__ __forceinline__ void cp16(unsigned dst, const void* src) {
    asm volatile("cp.async.cg.shared.global [%0], [%1], 16;" :: "r"(dst), "l"(src));
}
__device__ __forceinline__ void ldsm4(unsigned addr, unsigned& r0, unsigned& r1,
                                      unsigned& r2, unsigned& r3) {
    asm volatile("ldmatrix.sync.aligned.m8n8.x4.shared.b16 {%0,%1,%2,%3}, [%4];"
                 : "=r"(r0), "=r"(r1), "=r"(r2), "=r"(r3) : "r"(addr));
}
__device__ __forceinline__ int swoff(int m, int kc) {
    int p = m >> 1;
    int c = ((m & 1) << 2) | (kc ^ (p & 3));
    return p * 128 + c * 16;
}
__device__ __forceinline__ void fma8(float* acc, float wv, const uint4& v) {
    const __half2* h2 = (const __half2*)&v;
    float2 f0 = __half22float2(h2[0]), f1 = __half22float2(h2[1]);
    float2 f2 = __half22float2(h2[2]), f3 = __half22float2(h2[3]);
    acc[0] += wv * f0.x; acc[1] += wv * f0.y;
    acc[2] += wv * f1.x; acc[3] += wv * f1.y;
    acc[4] += wv * f2.x; acc[5] += wv * f2.y;
    acc[6] += wv * f3.x; acc[7] += wv * f3.y;
}

// ---------------- setup, split for stream overlap ----------------------------
// main stream: emb16 conversion only (what k_atom needs)
__global__ void k_setup_emb(const float* __restrict__ emb) {
    int idx = blockIdx.x * 1536 + threadIdx.x;  // 192 blocks
#pragma unroll
    for (int j = 0; j < 6; j++) {
        g_emb16[idx] = __float2half(emb[idx]);
        idx += 256;
    }
}

// side stream: zero-init + W convert/transpose + head + lprep
#define INIT_BLKS 352
#define WCONV_BLKS 192
__global__ void k_setup_rest(const float* __restrict__ W,
                             const float* __restrict__ W1, const float* __restrict__ b1,
                             const float* __restrict__ W2, const float* __restrict__ b2,
                             const float* __restrict__ We, const float* __restrict__ att_edge,
                             const float* __restrict__ bond_emb) {
    int t = threadIdx.x;  // 256
    int bid = blockIdx.x;
    if (bid < INIT_BLKS) {
        int i = bid * 256 + t;
        if (i < NN) { g_deg[i] = 0; g_cursor[i] = 0; }
        if (i < GG) { g_gsum[i] = 0.f; g_gcnt[i] = 0.f; }
        if (i < (NPAD - NN) * EMB) g_h16[NN * EMB + i] = __float2half(0.f);
        if (i < 3 * NN) { g_asL[i] = 0.f; g_adL[i] = 0.f; }
    } else if (bid < INIT_BLKS + WCONV_BLKS) {
        int wb = bid - INIT_BLKS;       // 0..191
        int l = wb >> 6;
        int rem = wb & 63;
        int kb = (rem & 7) * 32, nb = (rem >> 3) * 32;
        int tx = t & 31, ty = t >> 5;
        __shared__ float tile[32][33];
        for (int i = ty; i < 32; i += 8)
            tile[i][tx] = W[(size_t)l * EMB * EMB + (kb + i) * EMB + nb + tx];
        __syncthreads();
        for (int i = ty; i < 32; i += 8)
            g_w16[(size_t)l * EMB * EMB + (nb + i) * EMB + kb + tx] =
                __float2half(tile[tx][i]);
    } else if (bid == INIT_BLKS + WCONV_BLKS) {
        int c = t;
        float acc = 0.f;
#pragma unroll 8
        for (int j = 0; j < EMB; j++) acc += W1[c * EMB + j] * W2[j];
        g_wv[c] = acc;
        __shared__ float sh[EMB];
        sh[c] = b1[c] * W2[c];
        __syncthreads();
        for (int s = 128; s > 0; s >>= 1) {
            if (c < s) sh[c] += sh[c + s];
            __syncthreads();
        }
        if (c == 0) g_bconst = sh[0] + b2[0];
    } else {
        int l = bid - (INIT_BLKS + WCONV_BLKS + 1);
        __shared__ float wa[3];
        int w = t >> 5, lane = t & 31;
        if (w < 3) {
            float p = 0.f;
            for (int k = lane; k < EMB; k += 32)
                p += We[(l * 3 + w) * EMB + k] * att_edge[l * EMB + k];
            p = warp_sum(p);
            if (lane == 0) wa[w] = p;
        }
        __syncthreads();
        if (t < 48) {
            int j = t >> 4, v = t & 15;
            const float* be = bond_emb + ((size_t)(l * 3 + j) * 16 + v) * 3;
            g_dtable[l * 48 + t] = be[0] * wa[0] + be[1] * wa[1] + be[2] * wa[2];
        }
    }
}

// AtomEncoder, warp-per-node
__global__ void k_atom(const int* __restrict__ x) {
    int t = threadIdx.x;  // 256
    int lane = t & 31;
    int gw = blockIdx.x * 8 + (t >> 5);
    int xv = (lane < 9) ? x[gw * 9 + lane] : 0;
    float acc[8] = {0, 0, 0, 0, 0, 0, 0, 0};
#pragma unroll
    for (int i = 0; i < 9; i++) {
        int xi = __shfl_sync(0xffffffffu, xv, i);
        uint4 v = *(const uint4*)(g_emb16 + ((size_t)(i * 128 + xi)) * EMB + lane * 8);
        fma8(acc, 1.0f, v);
    }
    __half2 o[4];
    o[0] = __floats2half2_rn(acc[0], acc[1]);
    o[1] = __floats2half2_rn(acc[2], acc[3]);
    o[2] = __floats2half2_rn(acc[4], acc[5]);
    o[3] = __floats2half2_rn(acc[6], acc[7]);
    *(uint4*)(g_h16 + (size_t)gw * EMB + lane * 8) = *(uint4*)o;
}

// degree histogram, 4 edges per thread via int4 (EE = 480000 = 4*120000)
__global__ void k_hist(const int* __restrict__ dst) {
    int i = blockIdx.x * blockDim.x + threadIdx.x;
    if (i < EE / 4) {
        int4 d = *(const int4*)(dst + i * 4);
        atomicAdd(&g_deg[d.x], 1);
        atomicAdd(&g_deg[d.y], 1);
        atomicAdd(&g_deg[d.z], 1);
        atomicAdd(&g_deg[d.w], 1);
    }
}

// --------- 3-phase multi-block exclusive scan of g_deg -> g_rowptr ----------
__global__ void k_scan_red() {
    __shared__ int ws[32];
    int t = threadIdx.x, lane = t & 31, wid = t >> 5;
    int idx = blockIdx.x * 1024 + t;
    int v = (idx < NN) ? g_deg[idx] : 0;
    v = warp_sum_i(v);
    if (lane == 0) ws[wid] = v;
    __syncthreads();
    if (wid == 0) {
        int s = ws[lane];
        s = warp_sum_i(s);
        if (lane == 0) g_bsum[blockIdx.x] = s;
    }
}
__global__ void k_scan_top() {
    int lane = threadIdx.x;
    int v = (lane < SCB) ? g_bsum[lane] : 0;
    int x = v;
#pragma unroll
    for (int o = 1; o < 32; o <<= 1) {
        int y = __shfl_up_sync(0xffffffffu, x, o);
        if (lane >= o) x += y;
    }
    if (lane < SCB) g_boff[lane] = x - v;
}
__global__ void k_scan_low() {
    __shared__ int ws[32];
    int t = threadIdx.x, lane = t & 31, wid = t >> 5;
    int idx = blockIdx.x * 1024 + t;
    int v = (idx < NN) ? g_deg[idx] : 0;
    int x = v;
#pragma unroll
    for (int o = 1; o < 32; o <<= 1) {
        int y = __shfl_up_sync(0xffffffffu, x, o);
        if (lane >= o) x += y;
    }
    if (lane == 31) ws[wid] = x;
    __syncthreads();
    if (wid == 0) {
        int w = ws[lane];
#pragma unroll
        for (int o = 1; o < 32; o <<= 1) {
            int y = __shfl_up_sync(0xffffffffu, w, o);
            if (lane >= o) w += y;
        }
        ws[lane] = w;
    }
    __syncthreads();
    int incl = x + ((wid > 0) ? ws[wid - 1] : 0) + g_boff[blockIdx.x];
    if (idx < NN) g_rowptr[idx + 1] = incl;
    if (idx == 0) g_rowptr[0] = 0;
}

__global__ void k_scatter(const int* __restrict__ src, const int* __restrict__ dst,
                          const int* __restrict__ ea) {
    int e = blockIdx.x * blockDim.x + threadIdx.x;
    if (e >= EE) return;
    int d = dst[e];
    int pos = g_rowptr[d] + atomicAdd(&g_cursor[d], 1);
    unsigned packed = (unsigned)ea[e * 3 + 0] | ((unsigned)ea[e * 3 + 1] << 8) |
                      ((unsigned)ea[e * 3 + 2] << 16);
    g_csr[pos] = make_uint2((unsigned)src[e], packed);
}

// ------- fp16 GEMM + fused as/ad epilogue -----------------------------------
__global__ __launch_bounds__(256, 2) void k_mma(int l, const float* __restrict__ att_s,
                                                const float* __restrict__ att_d) {
    __shared__ __align__(16) char sm[49152];
    const unsigned smb = (unsigned)__cvta_generic_to_shared(sm);
    const int tid = threadIdx.x;
    const int lane = tid & 31;
    const int w = tid >> 5;
    const int tig = lane & 3, gid = lane >> 2;
    const int warp_m = w >> 2, warp_n = w & 3;
    const int r0 = blockIdx.x * 128, c0 = blockIdx.y * 128;

    const int lm = tid & 127;
    const int lkc = (tid >> 7) * 2;
    const __half* Ag = g_h16 + (size_t)(r0 + lm) * EMB + lkc * 8;
    const __half* Bg = g_w16 + (size_t)l * EMB * EMB + (size_t)(c0 + lm) * EMB + lkc * 8;
    const int sA0 = swoff(lm, lkc), sA1 = swoff(lm, lkc + 1);

    float acc[16][4];
#pragma unroll
    for (int i = 0; i < 16; i++)
#pragma unroll
        for (int j = 0; j < 4; j++) acc[i][j] = 0.f;

#define ISSUE(s)                                                          \
    {                                                                     \
        unsigned st = smb + ((s) % 3) * 16384;                            \
        cp16(st + sA0, Ag + (s) * 32);                                    \
        cp16(st + sA1, Ag + (s) * 32 + 8);                                \
        cp16(st + 8192 + sA0, Bg + (s) * 32);                             \
        cp16(st + 8192 + sA1, Bg + (s) * 32 + 8);                         \
        asm volatile("cp.async.commit_group;");                           \
    }

    ISSUE(0);
    ISSUE(1);

#pragma unroll
    for (int s = 0; s < 8; s++) {
        if (s < 7) asm volatile("cp.async.wait_group 1;");
        else       asm volatile("cp.async.wait_group 0;");
        __syncthreads();
        if (s + 2 < 8) ISSUE(s + 2);
        unsigned Ab = smb + (s % 3) * 16384;
        unsigned Bb = Ab + 8192;
#pragma unroll
        for (int kk = 0; kk < 32; kk += 16) {
            unsigned af[4][4], bf[4][2];
#pragma unroll
            for (int mt = 0; mt < 4; mt++) {
                int r = warp_m * 64 + mt * 16 + (lane & 15);
                int kc = (kk >> 3) + (lane >> 4);
                ldsm4(Ab + swoff(r, kc), af[mt][0], af[mt][1], af[mt][2], af[mt][3]);
            }
#pragma unroll
            for (int pr = 0; pr < 2; pr++) {
                int n = warp_n * 32 + pr * 16 + ((lane >> 4) & 1) * 8 + (lane & 7);
                int kc = (kk >> 3) + ((lane >> 3) & 1);
                ldsm4(Bb + swoff(n, kc), bf[2 * pr][0], bf[2 * pr][1],
                      bf[2 * pr + 1][0], bf[2 * pr + 1][1]);
            }
#pragma unroll
            for (int mt = 0; mt < 4; mt++)
#pragma unroll
                for (int nt = 0; nt < 4; nt++) {
                    float* c = acc[mt * 4 + nt];
                    asm volatile(
                        "mma.sync.aligned.m16n8k16.row.col.f32.f16.f16.f32 "
                        "{%0,%1,%2,%3}, {%4,%5,%6,%7}, {%8,%9}, {%0,%1,%2,%3};"
                        : "+f"(c[0]), "+f"(c[1]), "+f"(c[2]), "+f"(c[3])
                        : "r"(af[mt][0]), "r"(af[mt][1]), "r"(af[mt][2]), "r"(af[mt][3]),
                          "r"(bf[nt][0]), "r"(bf[nt][1]));
                }
        }
    }
#undef ISSUE
    float* asbuf = g_asL + l * NN;
    float* adbuf = g_adL + l * NN;
#pragma unroll
    for (int mt = 0; mt < 4; mt++) {
        int r = r0 + warp_m * 64 + mt * 16 + gid;
        float ps = 0.f, pd = 0.f, qs = 0.f, qd = 0.f;
#pragma unroll
        for (int nt = 0; nt < 4; nt++) {
            int c = c0 + warp_n * 32 + nt * 8 + 2 * tig;
            int ch = c >> 1;
            const float* a = acc[mt * 4 + nt];
            g_xlh[(size_t)r * 128 + ch] = __floats2half2_rn(a[0], a[1]);
            g_xlh[(size_t)(r + 8) * 128 + ch] = __floats2half2_rn(a[2], a[3]);
            float s0 = att_s[c], s1 = att_s[c + 1];
            float d0 = att_d[c], d1 = att_d[c + 1];
            ps += a[0] * s0 + a[1] * s1;
            pd += a[0] * d0 + a[1] * d1;
            qs += a[2] * s0 + a[3] * s1;
            qd += a[2] * d0 + a[3] * d1;
        }
#pragma unroll
        for (int o = 1; o <= 2; o <<= 1) {
            ps += __shfl_xor_sync(0xffffffffu, ps, o);
            pd += __shfl_xor_sync(0xffffffffu, pd, o);
            qs += __shfl_xor_sync(0xffffffffu, qs, o);
            qd += __shfl_xor_sync(0xffffffffu, qd, o);
        }
        if (tig == 0) {
            if (r < NN) { atomicAdd(asbuf + r, ps); atomicAdd(adbuf + r, pd); }
            if (r + 8 < NN) { atomicAdd(asbuf + r + 8, qs); atomicAdd(adbuf + r + 8, qd); }
        }
    }
}

// fused attention, single pass, BATCH-8 gather with uniform load guards
__global__ void k_att(const float* __restrict__ bias, int do_relu, int l,
                      const int* __restrict__ batch, int do_pool) {
    __shared__ float sdt[48];
    int t = threadIdx.x;
    if (t < 48) sdt[t] = g_dtable[l * 48 + t];
    __syncthreads();
    int gw = (blockIdx.x * blockDim.x + t) >> 5;
    int lane = t & 31;
    if (gw >= NN) return;
    const float* asv = g_asL + l * NN;
    const float* adv = g_adL + l * NN;
    int start = g_rowptr[gw], end = g_rowptr[gw + 1];
    float adn = adv[gw];
    // hoisted residual row load (latency hidden under gather loop)
    uint4 hv = *(const uint4*)(g_h16 + (size_t)gw * EMB + lane * 8);

    float acc[8] = {0, 0, 0, 0, 0, 0, 0, 0};
    float denom = 0.f, esum = 0.f;
    for (int cb = start; cb < end; cb += 32) {
        int pos = cb + lane;
        float p = 0.f;
        int s = 0;
        if (pos < end) {
            uint2 se = g_csr[pos];          // single 8B load: {src, attrs}
            s = (int)se.x;
            unsigned ea = se.y;
            float ed = sdt[ea & 15] + sdt[16 + ((ea >> 8) & 15)] +
                       sdt[32 + ((ea >> 16) & 15)];
            float a = asv[s] + adn + ed;
            a = (a >= 0.f) ? a : NEG_SLOPE * a;
            p = __expf(a);
            esum += ed;
        }
        denom += p;
        int cnt = min(32, end - cb);
        for (int i = 0; i < cnt; i += 8) {
            float w0 = __shfl_sync(0xffffffffu, p, i);
            int   s0 = __shfl_sync(0xffffffffu, s, i);
#define BCAST(j) \
            float w##j = (i + j < 32) ? __shfl_sync(0xffffffffu, p, i + j) : 0.f; \
            int   s##j = (i + j < 32) ? __shfl_sync(0xffffffffu, s, i + j) : 0;
            BCAST(1) BCAST(2) BCAST(3) BCAST(4) BCAST(5) BCAST(6) BCAST(7)
#undef BCAST
            uint4 v0 = make_uint4(0, 0, 0, 0), v1 = v0, v2 = v0, v3 = v0;
            uint4 v4 = v0, v5 = v0, v6 = v0, v7 = v0;
            if (w0 > 0.f) v0 = *(const uint4*)(g_xlh + (size_t)s0 * 128 + lane * 4);
            if (w1 > 0.f) v1 = *(const uint4*)(g_xlh + (size_t)s1 * 128 + lane * 4);
            if (w2 > 0.f) v2 = *(const uint4*)(g_xlh + (size_t)s2 * 128 + lane * 4);
            if (w3 > 0.f) v3 = *(const uint4*)(g_xlh + (size_t)s3 * 128 + lane * 4);
            if (w4 > 0.f) v4 = *(const uint4*)(g_xlh + (size_t)s4 * 128 + lane * 4);
            if (w5 > 0.f) v5 = *(const uint4*)(g_xlh + (size_t)s5 * 128 + lane * 4);
            if (w6 > 0.f) v6 = *(const uint4*)(g_xlh + (size_t)s6 * 128 + lane * 4);
            if (w7 > 0.f) v7 = *(const uint4*)(g_xlh + (size_t)s7 * 128 + lane * 4);
            fma8(acc, w0, v0);
            fma8(acc, w1, v1);
            fma8(acc, w2, v2);
            fma8(acc, w3, v3);
            fma8(acc, w4, v4);
            fma8(acc, w5, v5);
            fma8(acc, w6, v6);
            fma8(acc, w7, v7);
        }
    }
    // self loop
    {
        esum = warp_sum(esum);
        int deg = end - start;
        float selfa = asv[gw] + adn + esum / fmaxf((float)deg, 1.0f);
        selfa = (selfa >= 0.f) ? selfa : NEG_SLOPE * selfa;
        float wv = __expf(selfa);
        denom = warp_sum(denom) + wv;
        uint4 v = *(const uint4*)(g_xlh + (size_t)gw * 128 + lane * 4);
        fma8(acc, wv, v);
    }
    float inv = 1.0f / denom;
    const __half2* hh = (const __half2*)&hv;
    float2 hf0 = __half22float2(hh[0]), hf1 = __half22float2(hh[1]);
    float2 hf2 = __half22float2(hh[2]), hf3 = __half22float2(hh[3]);
    const float4* b4 = (const float4*)(bias + lane * 8);
    float4 b0 = b4[0], b1 = b4[1];
    float r[8];
    r[0] = acc[0] * inv + b0.x; r[1] = acc[1] * inv + b0.y;
    r[2] = acc[2] * inv + b0.z; r[3] = acc[3] * inv + b0.w;
    r[4] = acc[4] * inv + b1.x; r[5] = acc[5] * inv + b1.y;
    r[6] = acc[6] * inv + b1.z; r[7] = acc[7] * inv + b1.w;
    if (do_relu) {
#pragma unroll
        for (int j = 0; j < 8; j++) r[j] = fmaxf(r[j], 0.f);
    }
    r[0] += hf0.x; r[1] += hf0.y; r[2] += hf1.x; r[3] += hf1.y;
    r[4] += hf2.x; r[5] += hf2.y; r[6] += hf3.x; r[7] += hf3.y;
    if (do_pool) {
        const float4* w4 = (const float4*)(g_wv + lane * 8);
        float4 w0 = w4[0], w1 = w4[1];
        float sdot = r[0] * w0.x + r[1] * w0.y + r[2] * w0.z + r[3] * w0.w +
                     r[4] * w1.x + r[5] * w1.y + r[6] * w1.z + r[7] * w1.w;
        sdot = warp_sum(sdot);
        if (lane == 0) {
            int g = batch[gw];
            atomicAdd(&g_gsum[g], sdot);
            atomicAdd(&g_gcnt[g], 1.0f);
        }
    } else {
        __half2 o[4];
        o[0] = __floats2half2_rn(r[0], r[1]);
        o[1] = __floats2half2_rn(r[2], r[3]);
        o[2] = __floats2half2_rn(r[4], r[5]);
        o[3] = __floats2half2_rn(r[6], r[7]);
        *(uint4*)(g_h16 + (size_t)gw * EMB + lane * 8) = *(uint4*)o;
    }
}

__global__ void k_final(float* __restrict__ out) {
    int g = blockIdx.x * blockDim.x + threadIdx.x;
    if (g < GG) out[g] = g_gsum[g] / fmaxf(g_gcnt[g], 1.0f) + g_bconst;
}

// ---------------- launch -----------------------------------------------------
extern "C" void kernel_launch(void* const* d_in, const int* in_sizes, int n_in,
                              void* d_out, int out_size) {
    const int* x = (const int*)d_in[0];
    const int* edge_index = (const int*)d_in[1];
    const int* edge_attr = (const int*)d_in[2];
    const int* batch = (const int*)d_in[3];
    const float* atom_emb = (const float*)d_in[4];
    const float* bond_emb = (const float*)d_in[5];
    const float* W = (const float*)d_in[6];
    const float* att_src = (const float*)d_in[7];
    const float* att_dst = (const float*)d_in[8];
    const float* We = (const float*)d_in[9];
    const float* att_edge = (const float*)d_in[10];
    const float* bias = (const float*)d_in[11];
    const float* W1 = (const float*)d_in[12];
    const float* b1 = (const float*)d_in[13];
    const float* W2 = (const float*)d_in[14];
    const float* b2 = (const float*)d_in[15];
    float* out = (float*)d_out;

    const int* src = edge_index;
    const int* dst = edge_index + EE;

    // Side stream + events (host handles only; created fresh per call,
    // intentionally not destroyed while possibly participating in capture).
    cudaStream_t s2;
    cudaStreamCreateWithFlags(&s2, cudaStreamNonBlocking);
    cudaEvent_t efork, ew16, ejoin;
    cudaEventCreateWithFlags(&efork, cudaEventDisableTiming);
    cudaEventCreateWithFlags(&ew16, cudaEventDisableTiming);
    cudaEventCreateWithFlags(&ejoin, cudaEventDisableTiming);

    // fork immediately: side stream does init/wconv/head/lprep then CSR build
    cudaEventRecord(efork, 0);
    cudaStreamWaitEvent(s2, efork, 0);

    // main: emb convert -> atom encoder -> layer-0 GEMM
    k_setup_emb<<<192, 256>>>(atom_emb);
    k_setup_rest<<<INIT_BLKS + WCONV_BLKS + 4, 256, 0, s2>>>(W, W1, b1, W2, b2,
                                                             We, att_edge, bond_emb);
    cudaEventRecord(ew16, s2);       // w16 + deg=0 ready after this point
    k_atom<<<NWB, 256>>>(x);
    // side: CSR build chain (deg=0 ordered in-stream after setup_rest)
    k_hist<<<(EE / 4 + 255) / 256, 256, 0, s2>>>(dst);
    cudaStreamWaitEvent(0, ew16, 0);
    k_mma<<<dim3(NPAD / 128, EMB / 128), 256>>>(0, att_src, att_dst);
    k_scan_red<<<SCB, 1024, 0, s2>>>();
    k_scan_top<<<1, 32, 0, s2>>>();
    k_scan_low<<<SCB, 1024, 0, s2>>>();
    k_scatter<<<EBLOCKS, 256, 0, s2>>>(src, dst, edge_attr);
    cudaEventRecord(ejoin, s2);
    cudaStreamWaitEvent(0, ejoin, 0);

    for (int l = 0; l < 3; l++) {
        if (l > 0)
            k_mma<<<dim3(NPAD / 128, EMB / 128), 256>>>(l, att_src + l * EMB,
                                                        att_dst + l * EMB);
        k_att<<<NWB, 256>>>(bias + l * EMB, (l < 2) ? 1 : 0, l,
                            batch, (l == 2) ? 1 : 0);
    }

    k_final<<<2, 256>>>(out);
}